// round 11
// baseline (speedup 1.0000x reference)
#include <cuda_runtime.h>
#include <cuda_fp16.h>
#include <math_constants.h>
#include <cstdint>

#define NROWS 8192
#define NSPLIT 4
#define TILES 16                  // 128-wide col tiles per split
#define MARGIN_F 0.3f
#define NTHREADS 256
#define NCTAS (64 * NSPLIT)

#define ROWB 272                  // padded row stride bytes (256 used) -> conflict-free ldsm
#define CH (128 * ROWB)           // 34816 B per 128x128 fp16 chunk

// smem map (106.5 KB -> 2 CTAs/SM)
#define SM_PART 0                           // 512 floats = 2048
#define SM_A    2048                        // 34816 (resident)
#define SM_B    (SM_A + CH)                 // 2 x 34816 (double buffer)
#define SMEM_TOTAL (SM_B + 2 * CH)          // 106496

typedef unsigned long long u64;

__device__ __align__(16) unsigned char g_A[64 * CH];   // 2.1 MB (hi fp16)
__device__ __align__(16) unsigned char g_B[64 * CH];   // 2.1 MB
__device__ float g_sq1[NROWS];
__device__ float g_sq2[NROWS];
__device__ float g_posd2[NROWS];            // exact |z1_i - z2_i|^2
__device__ float g_rowmin[NSPLIT][NROWS];
__device__ int g_ctr;

__device__ __forceinline__ uint32_t smem_u32(const void* p) {
    uint32_t a;
    asm("{ .reg .u64 t; cvta.to.shared.u64 t, %1; cvt.u32.u64 %0, t; }" : "=r"(a) : "l"(p));
    return a;
}
__device__ __forceinline__ void cpasync16(uint32_t dst, const void* src) {
    asm volatile("cp.async.cg.shared.global [%0], [%1], 16;" :: "r"(dst), "l"(src));
}
#define CP_COMMIT() asm volatile("cp.async.commit_group;" ::: "memory")
#define CP_WAIT0()  asm volatile("cp.async.wait_group 0;"  ::: "memory")

__device__ __forceinline__ void ldsm_x4(uint32_t addr, uint32_t& r0, uint32_t& r1,
                                        uint32_t& r2, uint32_t& r3) {
    asm volatile("ldmatrix.sync.aligned.m8n8.x4.shared.b16 {%0,%1,%2,%3}, [%4];"
                 : "=r"(r0), "=r"(r1), "=r"(r2), "=r"(r3) : "r"(addr));
}
__device__ __forceinline__ void hmma(float* c, uint32_t a0, uint32_t a1, uint32_t a2,
                                     uint32_t a3, uint32_t b0, uint32_t b1) {
    asm volatile("mma.sync.aligned.m16n8k16.row.col.f32.f16.f16.f32 "
                 "{%0,%1,%2,%3}, {%4,%5,%6,%7}, {%8,%9}, {%0,%1,%2,%3};"
                 : "+f"(c[0]), "+f"(c[1]), "+f"(c[2]), "+f"(c[3])
                 : "r"(a0), "r"(a1), "r"(a2), "r"(a3), "r"(b0), "r"(b1));
}
__device__ __forceinline__ void hmma_z(float* c, uint32_t a0, uint32_t a1, uint32_t a2,
                                       uint32_t a3, uint32_t b0, uint32_t b1) {
    asm volatile("mma.sync.aligned.m16n8k16.row.col.f32.f16.f16.f32 "
                 "{%0,%1,%2,%3}, {%4,%5,%6,%7}, {%8,%9}, {%10,%10,%10,%10};"
                 : "=f"(c[0]), "=f"(c[1]), "=f"(c[2]), "=f"(c[3])
                 : "r"(a0), "r"(a1), "r"(a2), "r"(a3), "r"(b0), "r"(b1), "f"(0.f));
}

// ---------------------------------------------------------------------------
// Prep: one warp per row. sq norms, EXACT pos d2 = |z1-z2|^2, fp16 hi images.
// ---------------------------------------------------------------------------
__global__ void prep_kernel(const float* __restrict__ z1, const float* __restrict__ z2) {
    const int gw = (blockIdx.x * blockDim.x + threadIdx.x) >> 5;
    const int l  = threadIdx.x & 31;
    if (gw >= NROWS) return;
    const int rb = gw >> 7, r = gw & 127;
    const size_t rowoff = (size_t)rb * CH + (size_t)r * ROWB + (size_t)l * 8;

    float4 v1 = reinterpret_cast<const float4*>(z1 + (size_t)gw * 128)[l];
    float4 v2 = reinterpret_cast<const float4*>(z2 + (size_t)gw * 128)[l];
    float x1[4] = {v1.x, v1.y, v1.z, v1.w};
    float x2[4] = {v2.x, v2.y, v2.z, v2.w};

    float sq1 = 0.f, sq2 = 0.f, dd = 0.f;
    u64 hq1 = 0, hq2 = 0;
    #pragma unroll
    for (int t = 0; t < 4; t++) {
        sq1 += x1[t] * x1[t];
        sq2 += x2[t] * x2[t];
        const float d = x1[t] - x2[t];
        dd += d * d;
        hq1 |= (u64)__half_as_ushort(__float2half_rn(x1[t])) << (16 * t);
        hq2 |= (u64)__half_as_ushort(__float2half_rn(x2[t])) << (16 * t);
    }
    #pragma unroll
    for (int o = 16; o; o >>= 1) {
        sq1 += __shfl_xor_sync(0xffffffffu, sq1, o);
        sq2 += __shfl_xor_sync(0xffffffffu, sq2, o);
        dd  += __shfl_xor_sync(0xffffffffu, dd, o);
    }
    *(u64*)(g_A + rowoff) = hq1;
    *(u64*)(g_B + rowoff) = hq2;
    if (l == 0) { g_sq1[gw] = sq1; g_sq2[gw] = sq2; g_posd2[gw] = dd; }
}

// ---------------------------------------------------------------------------
// Main: 256 CTAs (64 row-blocks x 4 col-splits), 8 warps, warp tile 64x32.
// 2 CTAs/SM (106.5 KB smem). sq2 prefetched to regs per tile.
// ---------------------------------------------------------------------------
__global__ __launch_bounds__(NTHREADS, 2) void tl_gemm_kernel(float* __restrict__ out) {
    extern __shared__ char smem[];
    float* partmin = (float*)(smem + SM_PART);
    const uint32_t smA = smem_u32(smem) + SM_A;
    const uint32_t smB = smem_u32(smem) + SM_B;

    const int tid = threadIdx.x;
    const int l = tid & 31, wid = tid >> 5;
    const int wr = wid & 1, wc = wid >> 1;       // 2 row halves x 4 col groups
    const int rowBase = blockIdx.x * 128;
    const int sp = blockIdx.y;

    // prologue: A chunk (resident) + B tile 0
    {
        const unsigned char* Ag = g_A + (size_t)blockIdx.x * CH;
        #pragma unroll
        for (int e = 0; e < 9; e++) {                // 2176 x 16B
            int idx = e * NTHREADS + tid;
            if (idx < CH / 16) cpasync16(smA + idx * 16, Ag + (size_t)idx * 16);
        }
        const unsigned char* Bg = g_B + (size_t)(sp * TILES) * CH;
        #pragma unroll
        for (int e = 0; e < 9; e++) {
            int idx = e * NTHREADS + tid;
            if (idx < CH / 16) cpasync16(smB + idx * 16, Bg + (size_t)idx * 16);
        }
        CP_COMMIT();
    }

    float rminL[4], rminH[4];
    #pragma unroll
    for (int i = 0; i < 4; i++) { rminL[i] = CUDART_INF_F; rminH[i] = CUDART_INF_F; }

    const uint32_t aOff = (uint32_t)((wr * 64 + (l & 15)) * ROWB + (l >> 4) * 16);
    const uint32_t bOff = (uint32_t)((wc * 32 + (l & 15)) * ROWB + (l >> 4) * 16);
    const uint32_t aHi = smA + aOff;
    const int mL = rowBase + wr * 64 + (l >> 2);
    const int nb = wc * 32 + 2 * (l & 3);

    float acc[4][4][4];

    for (int jt = 0; jt < TILES; jt++) {
        const int colT = (sp * TILES + jt) * 128;

        // prefetch sq2 values for this tile's epilogue (L2 -> regs, overlaps k-loop)
        float2 q2p[4];
        #pragma unroll
        for (int j = 0; j < 4; j++)
            q2p[j] = *(const float2*)(g_sq2 + colT + nb + j * 8);

        CP_WAIT0();
        __syncthreads();

        if (jt + 1 < TILES) {   // prefetch next 34KB B chunk
            const unsigned char* Bg = g_B + (size_t)(sp * TILES + jt + 1) * CH;
            const uint32_t dst = smB + (uint32_t)(((jt + 1) & 1) ? CH : 0);
            #pragma unroll
            for (int e = 0; e < 9; e++) {
                int idx = e * NTHREADS + tid;
                if (idx < CH / 16) cpasync16(dst + idx * 16, Bg + (size_t)idx * 16);
            }
            CP_COMMIT();
        }

        const uint32_t bC = smB + (uint32_t)((jt & 1) ? CH : 0) + bOff;

        #pragma unroll
        for (int ks = 0; ks < 8; ks++) {
            uint32_t b[8];
            ldsm_x4(bC + ks * 32, b[0], b[1], b[2], b[3]);                 // n0-15
            ldsm_x4(bC + 16 * ROWB + ks * 32, b[4], b[5], b[6], b[7]);     // n16-31
            #pragma unroll
            for (int i = 0; i < 4; i++) {
                uint32_t a0, a1, a2, a3;
                ldsm_x4(aHi + i * 16 * ROWB + ks * 32, a0, a1, a2, a3);
                if (ks == 0) {
                    hmma_z(acc[i][0], a0, a1, a2, a3, b[0], b[2]);
                    hmma_z(acc[i][1], a0, a1, a2, a3, b[1], b[3]);
                    hmma_z(acc[i][2], a0, a1, a2, a3, b[4], b[6]);
                    hmma_z(acc[i][3], a0, a1, a2, a3, b[5], b[7]);
                } else {
                    hmma(acc[i][0], a0, a1, a2, a3, b[0], b[2]);
                    hmma(acc[i][1], a0, a1, a2, a3, b[1], b[3]);
                    hmma(acc[i][2], a0, a1, a2, a3, b[4], b[6]);
                    hmma(acc[i][3], a0, a1, a2, a3, b[5], b[7]);
                }
            }
        }

        // ---- epilogue: v = sq2 - 2*dot, inf-mask diagonal, running min
        {
            const bool diagT = (colT == rowBase);
            #pragma unroll
            for (int j = 0; j < 4; j++) {
                const int n0 = colT + nb + j * 8;
                #pragma unroll
                for (int i = 0; i < 4; i++) {
                    float v0 = fmaf(-2.f, acc[i][j][0], q2p[j].x);
                    float v1 = fmaf(-2.f, acc[i][j][1], q2p[j].y);
                    float v2 = fmaf(-2.f, acc[i][j][2], q2p[j].x);
                    float v3 = fmaf(-2.f, acc[i][j][3], q2p[j].y);
                    if (diagT) {
                        const int m0 = mL + i * 16, m1 = m0 + 8;
                        if (n0 == m0)     v0 = CUDART_INF_F;
                        if (n0 + 1 == m0) v1 = CUDART_INF_F;
                        if (n0 == m1)     v2 = CUDART_INF_F;
                        if (n0 + 1 == m1) v3 = CUDART_INF_F;
                    }
                    rminL[i] = fminf(rminL[i], fminf(v0, v1));
                    rminH[i] = fminf(rminH[i], fminf(v2, v3));
                }
            }
        }
    }

    // cross-lane then cross-warp-column min reduction
    #pragma unroll
    for (int i = 0; i < 4; i++) {
        float vL = rminL[i], vH = rminH[i];
        vL = fminf(vL, __shfl_xor_sync(0xffffffffu, vL, 1));
        vL = fminf(vL, __shfl_xor_sync(0xffffffffu, vL, 2));
        vH = fminf(vH, __shfl_xor_sync(0xffffffffu, vH, 1));
        vH = fminf(vH, __shfl_xor_sync(0xffffffffu, vH, 2));
        if ((l & 3) == 0) {
            const int r = wr * 64 + i * 16 + (l >> 2);
            partmin[wc * 128 + r]     = vL;
            partmin[wc * 128 + r + 8] = vH;
        }
    }
    __syncthreads();
    if (tid < 128) {
        float m = fminf(fminf(partmin[tid], partmin[128 + tid]),
                        fminf(partmin[256 + tid], partmin[384 + tid]));
        g_rowmin[sp][rowBase + tid] = m;
    }

    // ---- fused finalize: last CTA computes the loss
    __threadfence();
    __shared__ int isLast;
    __syncthreads();
    if (tid == 0) {
        int v = atomicAdd(&g_ctr, 1);
        isLast = (v == NCTAS - 1);
    }
    __syncthreads();
    if (isLast) {
        __threadfence();
        float s = 0.f;
        for (int i = tid; i < NROWS; i += NTHREADS) {
            float m = fminf(fminf(g_rowmin[0][i], g_rowmin[1][i]),
                            fminf(g_rowmin[2][i], g_rowmin[3][i]));
            const float lv = sqrtf(fmaxf(g_posd2[i], 0.f))
                           - sqrtf(fmaxf(g_sq1[i] + m, 0.f)) + MARGIN_F;
            s += fmaxf(lv, 0.f);
        }
        partmin[tid] = s;
        __syncthreads();
        #pragma unroll
        for (int o = 128; o; o >>= 1) {
            if (tid < o) partmin[tid] += partmin[tid + o];
            __syncthreads();
        }
        if (tid == 0) { out[0] = partmin[0] / (float)NROWS; g_ctr = 0; }
    }
}

// ---------------------------------------------------------------------------
extern "C" void kernel_launch(void* const* d_in, const int* in_sizes, int n_in,
                              void* d_out, int out_size) {
    const float* z1 = (const float*)d_in[0];
    const float* z2 = (const float*)d_in[1];
    float* out = (float*)d_out;

    cudaFuncSetAttribute(tl_gemm_kernel,
                         cudaFuncAttributeMaxDynamicSharedMemorySize, SMEM_TOTAL);

    prep_kernel<<<NROWS / 8, 256>>>(z1, z2);
    tl_gemm_kernel<<<dim3(64, NSPLIT), NTHREADS, SMEM_TOTAL>>>(out);
}

// round 12
// speedup vs baseline: 1.2501x; 1.2501x over previous
#include <cuda_runtime.h>
#include <cuda_fp16.h>
#include <math_constants.h>
#include <cstdint>

#define NROWS 8192
#define MARGIN_F 0.3f
#define NTHREADS 512
#define NCTAS 148
#define TOTAL_TILES 4096          // 64 rowblocks x 64 coltiles
#define CHUNK 28                  // ceil(4096/148)

#define ROWB 272                  // padded row stride bytes (256 used) -> conflict-free ldsm
#define CH (128 * ROWB)           // 34816 B per 128x128 fp16 chunk

// smem map: reduce buf | q2 double buf | A double buf | B double buf
#define SM_RED 0                            // 512 floats = 2048
#define SM_Q2  2048                         // 2 x 512 B
#define SM_A   4096                         // 2 x CH
#define SM_B   (SM_A + 2 * CH)              // 2 x CH
#define SMEM_TOTAL (SM_B + 2 * CH)          // 143360

typedef unsigned long long u64;

__device__ __align__(16) unsigned char g_A[64 * CH];   // 2.1 MB (hi fp16)
__device__ __align__(16) unsigned char g_B[64 * CH];   // 2.1 MB
__device__ float g_sq1[NROWS];
__device__ float g_sq2[NROWS];
__device__ float g_posd2[NROWS];            // exact |z1_i - z2_i|^2
__device__ unsigned int g_rowminbits[NROWS];
__device__ int g_ctr;

__device__ __forceinline__ uint32_t fenc(float f) {
    uint32_t b = __float_as_uint(f);
    return (b & 0x80000000u) ? ~b : (b | 0x80000000u);
}
__device__ __forceinline__ float fdec(uint32_t u) {
    return (u >> 31) ? __uint_as_float(u & 0x7FFFFFFFu) : __uint_as_float(~u);
}

__device__ __forceinline__ uint32_t smem_u32(const void* p) {
    uint32_t a;
    asm("{ .reg .u64 t; cvta.to.shared.u64 t, %1; cvt.u32.u64 %0, t; }" : "=r"(a) : "l"(p));
    return a;
}
__device__ __forceinline__ void cpasync16(uint32_t dst, const void* src) {
    asm volatile("cp.async.cg.shared.global [%0], [%1], 16;" :: "r"(dst), "l"(src));
}
#define CP_COMMIT() asm volatile("cp.async.commit_group;" ::: "memory")
#define CP_WAIT0()  asm volatile("cp.async.wait_group 0;"  ::: "memory")

__device__ __forceinline__ void ldsm_x4(uint32_t addr, uint32_t& r0, uint32_t& r1,
                                        uint32_t& r2, uint32_t& r3) {
    asm volatile("ldmatrix.sync.aligned.m8n8.x4.shared.b16 {%0,%1,%2,%3}, [%4];"
                 : "=r"(r0), "=r"(r1), "=r"(r2), "=r"(r3) : "r"(addr));
}
__device__ __forceinline__ void hmma(float* c, uint32_t a0, uint32_t a1, uint32_t a2,
                                     uint32_t a3, uint32_t b0, uint32_t b1) {
    asm volatile("mma.sync.aligned.m16n8k16.row.col.f32.f16.f16.f32 "
                 "{%0,%1,%2,%3}, {%4,%5,%6,%7}, {%8,%9}, {%0,%1,%2,%3};"
                 : "+f"(c[0]), "+f"(c[1]), "+f"(c[2]), "+f"(c[3])
                 : "r"(a0), "r"(a1), "r"(a2), "r"(a3), "r"(b0), "r"(b1));
}
__device__ __forceinline__ void hmma_z(float* c, uint32_t a0, uint32_t a1, uint32_t a2,
                                       uint32_t a3, uint32_t b0, uint32_t b1) {
    asm volatile("mma.sync.aligned.m16n8k16.row.col.f32.f16.f16.f32 "
                 "{%0,%1,%2,%3}, {%4,%5,%6,%7}, {%8,%9}, {%10,%10,%10,%10};"
                 : "=f"(c[0]), "=f"(c[1]), "=f"(c[2]), "=f"(c[3])
                 : "r"(a0), "r"(a1), "r"(a2), "r"(a3), "r"(b0), "r"(b1), "f"(0.f));
}

// ---------------------------------------------------------------------------
// Prep: one warp per row. sq norms, EXACT pos d2, fp16 hi images, rowmin init.
// ---------------------------------------------------------------------------
__global__ void prep_kernel(const float* __restrict__ z1, const float* __restrict__ z2) {
    const int gw = (blockIdx.x * blockDim.x + threadIdx.x) >> 5;
    const int l  = threadIdx.x & 31;
    if (gw >= NROWS) return;
    const int rb = gw >> 7, r = gw & 127;
    const size_t rowoff = (size_t)rb * CH + (size_t)r * ROWB + (size_t)l * 8;

    float4 v1 = reinterpret_cast<const float4*>(z1 + (size_t)gw * 128)[l];
    float4 v2 = reinterpret_cast<const float4*>(z2 + (size_t)gw * 128)[l];
    float x1[4] = {v1.x, v1.y, v1.z, v1.w};
    float x2[4] = {v2.x, v2.y, v2.z, v2.w};

    float sq1 = 0.f, sq2 = 0.f, dd = 0.f;
    u64 hq1 = 0, hq2 = 0;
    #pragma unroll
    for (int t = 0; t < 4; t++) {
        sq1 += x1[t] * x1[t];
        sq2 += x2[t] * x2[t];
        const float d = x1[t] - x2[t];
        dd += d * d;
        hq1 |= (u64)__half_as_ushort(__float2half_rn(x1[t])) << (16 * t);
        hq2 |= (u64)__half_as_ushort(__float2half_rn(x2[t])) << (16 * t);
    }
    #pragma unroll
    for (int o = 16; o; o >>= 1) {
        sq1 += __shfl_xor_sync(0xffffffffu, sq1, o);
        sq2 += __shfl_xor_sync(0xffffffffu, sq2, o);
        dd  += __shfl_xor_sync(0xffffffffu, dd, o);
    }
    *(u64*)(g_A + rowoff) = hq1;
    *(u64*)(g_B + rowoff) = hq2;
    if (l == 0) {
        g_sq1[gw] = sq1; g_sq2[gw] = sq2; g_posd2[gw] = dd;
        g_rowminbits[gw] = 0xFF800000u;     // fenc(+inf)
    }
}

// ---------------------------------------------------------------------------
// Main: persistent 148 CTAs, 16 warps, warp tile 32x32, 28 contiguous tiles
// per CTA (rb-major). A frags register-resident per rowblock. atomicMin rows.
// ---------------------------------------------------------------------------
__global__ __launch_bounds__(NTHREADS, 1) void tl_gemm_kernel(float* __restrict__ out) {
    extern __shared__ char smem[];
    float* red = (float*)(smem + SM_RED);
    const uint32_t sbase = smem_u32(smem);
    const uint32_t smQ2 = sbase + SM_Q2;
    const uint32_t smA = sbase + SM_A;
    const uint32_t smB = sbase + SM_B;

    const int tid = threadIdx.x;
    const int l = tid & 31, wid = tid >> 5;
    const int wr = wid & 3, wc = wid >> 2;       // 4 row groups x 4 col groups

    const int start = blockIdx.x * CHUNK;
    const int end   = (start + CHUNK < TOTAL_TILES) ? start + CHUNK : TOTAL_TILES;

    const uint32_t aOff = (uint32_t)((wr * 32 + (l & 15)) * ROWB + (l >> 4) * 16);
    const uint32_t bOff = (uint32_t)((wc * 32 + (l & 15)) * ROWB + (l >> 4) * 16);
    const int nb = wc * 32 + 2 * (l & 3);

    if (start < end) {
        // prologue: A(rb0) -> Abuf0, B(jt0)+q2 -> buf0
        {
            const int rb0 = start >> 6, jt0 = start & 63;
            const unsigned char* Ag = g_A + (size_t)rb0 * CH;
            const unsigned char* Bg = g_B + (size_t)jt0 * CH;
            #pragma unroll
            for (int e = 0; e < 5; e++) {
                int idx = e * NTHREADS + tid;
                if (idx < CH / 16) {
                    cpasync16(smA + idx * 16, Ag + (size_t)idx * 16);
                    cpasync16(smB + idx * 16, Bg + (size_t)idx * 16);
                }
            }
            if (tid < 32) cpasync16(smQ2 + tid * 16, g_sq2 + jt0 * 128 + tid * 4);
            CP_COMMIT();
        }

        float rminL[2], rminH[2];
        #pragma unroll
        for (int i = 0; i < 2; i++) { rminL[i] = CUDART_INF_F; rminH[i] = CUDART_INF_F; }

        uint32_t af[2][8][4];      // A fragments for current rowblock (64 regs)
        int curA = 0;
        bool needA = true;
        float acc[2][4][4];

        for (int t = start; t < end; t++) {
            const int rb = t >> 6, jt = t & 63;
            const int bbuf = (t - start) & 1;
            const int rowBase = rb * 128, colT = jt * 128;

            CP_WAIT0();
            __syncthreads();

            if (t + 1 < end) {    // prefetch next tile (B + q2, and A if rb changes)
                const int rb1 = (t + 1) >> 6, jt1 = (t + 1) & 63;
                const int nbuf = bbuf ^ 1;
                const unsigned char* Bg = g_B + (size_t)jt1 * CH;
                const uint32_t dstB = smB + (uint32_t)(nbuf ? CH : 0);
                #pragma unroll
                for (int e = 0; e < 5; e++) {
                    int idx = e * NTHREADS + tid;
                    if (idx < CH / 16) cpasync16(dstB + idx * 16, Bg + (size_t)idx * 16);
                }
                if (tid < 32)
                    cpasync16(smQ2 + (nbuf ? 512u : 0u) + tid * 16,
                              g_sq2 + jt1 * 128 + tid * 4);
                if (rb1 != rb) {
                    const unsigned char* Ag = g_A + (size_t)rb1 * CH;
                    const uint32_t dstA = smA + (uint32_t)(curA ? 0 : CH);
                    #pragma unroll
                    for (int e = 0; e < 5; e++) {
                        int idx = e * NTHREADS + tid;
                        if (idx < CH / 16) cpasync16(dstA + idx * 16, Ag + (size_t)idx * 16);
                    }
                }
                CP_COMMIT();
            }

            if (needA) {          // hoist A fragments for this rowblock
                const uint32_t aHi = smA + (uint32_t)(curA ? CH : 0) + aOff;
                #pragma unroll
                for (int i = 0; i < 2; i++)
                    #pragma unroll
                    for (int ks = 0; ks < 8; ks++)
                        ldsm_x4(aHi + i * 16 * ROWB + ks * 32,
                                af[i][ks][0], af[i][ks][1], af[i][ks][2], af[i][ks][3]);
                needA = false;
            }

            const uint32_t bC = smB + (uint32_t)(bbuf ? CH : 0) + bOff;

            #pragma unroll
            for (int ks = 0; ks < 8; ks++) {
                uint32_t b[8];
                ldsm_x4(bC + ks * 32, b[0], b[1], b[2], b[3]);                 // n0-15
                ldsm_x4(bC + 16 * ROWB + ks * 32, b[4], b[5], b[6], b[7]);     // n16-31
                #pragma unroll
                for (int i = 0; i < 2; i++) {
                    if (ks == 0) {
                        hmma_z(acc[i][0], af[i][0][0], af[i][0][1], af[i][0][2], af[i][0][3], b[0], b[2]);
                        hmma_z(acc[i][1], af[i][0][0], af[i][0][1], af[i][0][2], af[i][0][3], b[1], b[3]);
                        hmma_z(acc[i][2], af[i][0][0], af[i][0][1], af[i][0][2], af[i][0][3], b[4], b[6]);
                        hmma_z(acc[i][3], af[i][0][0], af[i][0][1], af[i][0][2], af[i][0][3], b[5], b[7]);
                    } else {
                        hmma(acc[i][0], af[i][ks][0], af[i][ks][1], af[i][ks][2], af[i][ks][3], b[0], b[2]);
                        hmma(acc[i][1], af[i][ks][0], af[i][ks][1], af[i][ks][2], af[i][ks][3], b[1], b[3]);
                        hmma(acc[i][2], af[i][ks][0], af[i][ks][1], af[i][ks][2], af[i][ks][3], b[4], b[6]);
                        hmma(acc[i][3], af[i][ks][0], af[i][ks][1], af[i][ks][2], af[i][ks][3], b[5], b[7]);
                    }
                }
            }

            // ---- epilogue: v = sq2 - 2*dot, inf-mask diagonal, running min
            {
                const bool diagT = (colT == rowBase);
                const int mL = rowBase + wr * 32 + (l >> 2);
                const uint32_t q2b = smQ2 + (bbuf ? 512u : 0u);
                #pragma unroll
                for (int j = 0; j < 4; j++) {
                    const int n0 = colT + nb + j * 8;
                    float2 q2;
                    asm volatile("ld.shared.v2.f32 {%0,%1}, [%2];"
                                 : "=f"(q2.x), "=f"(q2.y)
                                 : "r"(q2b + (uint32_t)(nb + j * 8) * 4u));
                    #pragma unroll
                    for (int i = 0; i < 2; i++) {
                        float v0 = fmaf(-2.f, acc[i][j][0], q2.x);
                        float v1 = fmaf(-2.f, acc[i][j][1], q2.y);
                        float v2 = fmaf(-2.f, acc[i][j][2], q2.x);
                        float v3 = fmaf(-2.f, acc[i][j][3], q2.y);
                        if (diagT) {
                            const int m0 = mL + i * 16, m1 = m0 + 8;
                            if (n0 == m0)     v0 = CUDART_INF_F;
                            if (n0 + 1 == m0) v1 = CUDART_INF_F;
                            if (n0 == m1)     v2 = CUDART_INF_F;
                            if (n0 + 1 == m1) v3 = CUDART_INF_F;
                        }
                        rminL[i] = fminf(rminL[i], fminf(v0, v1));
                        rminH[i] = fminf(rminH[i], fminf(v2, v3));
                    }
                }
            }

            // flush row mins when leaving this rowblock (or at chunk end)
            if (t + 1 >= end || ((t + 1) >> 6) != rb) {
                #pragma unroll
                for (int i = 0; i < 2; i++) {
                    float vL = rminL[i], vH = rminH[i];
                    vL = fminf(vL, __shfl_xor_sync(0xffffffffu, vL, 1));
                    vL = fminf(vL, __shfl_xor_sync(0xffffffffu, vL, 2));
                    vH = fminf(vH, __shfl_xor_sync(0xffffffffu, vH, 1));
                    vH = fminf(vH, __shfl_xor_sync(0xffffffffu, vH, 2));
                    if ((l & 3) == 0) {
                        const int r = rowBase + wr * 32 + i * 16 + (l >> 2);
                        atomicMin(&g_rowminbits[r], fenc(vL));
                        atomicMin(&g_rowminbits[r + 8], fenc(vH));
                    }
                    rminL[i] = CUDART_INF_F; rminH[i] = CUDART_INF_F;
                }
                if (t + 1 < end) { curA ^= 1; needA = true; }
            }
        }
    }

    // ---- fused finalize: last CTA computes the loss
    __threadfence();
    __shared__ int isLast;
    __syncthreads();
    if (tid == 0) {
        int v = atomicAdd(&g_ctr, 1);
        isLast = (v == NCTAS - 1);
    }
    __syncthreads();
    if (isLast) {
        __threadfence();
        float s = 0.f;
        for (int i = tid; i < NROWS; i += NTHREADS) {
            const float m = fdec(g_rowminbits[i]);
            const float lv = sqrtf(fmaxf(g_posd2[i], 0.f))
                           - sqrtf(fmaxf(g_sq1[i] + m, 0.f)) + MARGIN_F;
            s += fmaxf(lv, 0.f);
        }
        red[tid] = s;
        __syncthreads();
        #pragma unroll
        for (int o = 256; o; o >>= 1) {
            if (tid < o) red[tid] += red[tid + o];
            __syncthreads();
        }
        if (tid == 0) { out[0] = red[0] / (float)NROWS; g_ctr = 0; }
    }
}

// ---------------------------------------------------------------------------
extern "C" void kernel_launch(void* const* d_in, const int* in_sizes, int n_in,
                              void* d_out, int out_size) {
    const float* z1 = (const float*)d_in[0];
    const float* z2 = (const float*)d_in[1];
    float* out = (float*)d_out;

    cudaFuncSetAttribute(tl_gemm_kernel,
                         cudaFuncAttributeMaxDynamicSharedMemorySize, SMEM_TOTAL);

    prep_kernel<<<NROWS / 8, 256>>>(z1, z2);
    tl_gemm_kernel<<<NCTAS, NTHREADS, SMEM_TOTAL>>>(out);
}